// round 6
// baseline (speedup 1.0000x reference)
#include <cuda_runtime.h>

#define N_NODES 200000
#define N_EDGES 3200000
#define SCAN_BLOCKS 196   // ceil(200000 / 1024); all blocks co-resident (<= 148*8)
#define BUILD_THREADS (SCAN_BLOCKS * 256)

// ---------------- scratch (device globals; zero-initialized at module load) ----------------
__device__ __align__(16) int    g_deg[N_NODES];      // invariant: zero at kernel_launch entry
__device__ __align__(16) int    g_off[N_NODES + 1];
__device__ __align__(16) int    g_cursor[N_NODES];
__device__ __align__(16) int    g_flag[256];         // invariant: zero at kernel_launch entry
__device__ volatile int         g_barcnt[2];         // invariant: zero at kernel_launch entry (reset by k_conv0)
__device__ __align__(16) int    g_src[N_EDGES];
__device__ __align__(16) float2 g_kw[N_EDGES];
__device__ __align__(16) float  g_h16[N_NODES * 16];
__device__ __align__(16) float  g_h32[N_NODES * 32];
__device__ __align__(16) float  g_h64[N_NODES * 64];

typedef unsigned long long ull;

__device__ __forceinline__ ull fma2(ull a, ull b, ull c) {
    ull d;
    asm("fma.rn.f32x2 %0, %1, %2, %3;" : "=l"(d) : "l"(a), "l"(b), "l"(c));
    return d;
}
__device__ __forceinline__ ull pack2(float x, float y) {
    ull r;
    asm("mov.b64 %0, {%1, %2};" : "=l"(r) : "f"(x), "f"(y));
    return r;
}
__device__ __forceinline__ float2 unpack2(ull v) {
    float2 r;
    asm("mov.b64 {%0, %1}, %2;" : "=f"(r.x), "=f"(r.y) : "l"(v));
    return r;
}

// simple arrive-and-spin grid barrier; counters are monotonic within a launch and
// reset to 0 by the NEXT kernel in stream order (k_conv0), so graph replays are safe.
__device__ __forceinline__ void grid_barrier(volatile int* cnt) {
    __syncthreads();
    if (threadIdx.x == 0) {
        __threadfence();
        atomicAdd((int*)cnt, 1);
        while (*cnt < SCAN_BLOCKS) { }
        __threadfence();
    }
    __syncthreads();
}

// ---------------- fused CSR build: hist -> scan(lookback) -> scatter ----------------
__global__ void __launch_bounds__(256) k_build(const int* __restrict__ ei,
                                               const float* __restrict__ Kw) {
    int t = threadIdx.x;
    int b = blockIdx.x;
    int gtid = b * 256 + t;

    // ---- phase 1: degree histogram (grid-stride) ----
    for (int e = gtid; e < N_EDGES; e += BUILD_THREADS)
        atomicAdd(&g_deg[ei[N_EDGES + e]], 1);

    grid_barrier(&g_barcnt[0]);

    // ---- phase 2: block-local scan + spin-flag lookback ----
    __shared__ int sh[256];
    __shared__ int red[8];
    int base = b * 1024 + t * 4;
    int v0 = 0, v1 = 0, v2 = 0, v3 = 0;
    if (base + 0 < N_NODES) v0 = g_deg[base + 0];
    if (base + 1 < N_NODES) v1 = g_deg[base + 1];
    if (base + 2 < N_NODES) v2 = g_deg[base + 2];
    if (base + 3 < N_NODES) v3 = g_deg[base + 3];
    int tot = v0 + v1 + v2 + v3;
    sh[t] = tot;
    __syncthreads();
    for (int d = 1; d < 256; d <<= 1) {
        int xv = (t >= d) ? sh[t - d] : 0;
        __syncthreads();
        sh[t] += xv;
        __syncthreads();
    }
    if (t == 255) ((volatile int*)g_flag)[b] = sh[255] + 1;  // publish block total

    int v = 0;
    if (t < b) {
        volatile int* f = (volatile int*)g_flag;
        int fv;
        while ((fv = f[t]) == 0) {}
        v = fv - 1;
    }
#pragma unroll
    for (int d = 16; d > 0; d >>= 1) v += __shfl_down_sync(0xffffffffu, v, d);
    if ((t & 31) == 0) red[t >> 5] = v;
    __syncthreads();
    int prefix = red[0] + red[1] + red[2] + red[3] + red[4] + red[5] + red[6] + red[7];

    int excl = sh[t] - tot + prefix;
    int e0 = excl, e1 = excl + v0, e2 = excl + v0 + v1, e3 = excl + v0 + v1 + v2;
    if (base + 0 < N_NODES) { g_off[base + 0] = e0; g_cursor[base + 0] = e0; g_deg[base + 0] = 0; }
    if (base + 1 < N_NODES) { g_off[base + 1] = e1; g_cursor[base + 1] = e1; g_deg[base + 1] = 0; }
    if (base + 2 < N_NODES) { g_off[base + 2] = e2; g_cursor[base + 2] = e2; g_deg[base + 2] = 0; }
    if (base + 3 < N_NODES) { g_off[base + 3] = e3; g_cursor[base + 3] = e3; g_deg[base + 3] = 0; }
    if (b == 0 && t == 0) g_off[N_NODES] = N_EDGES;

    grid_barrier(&g_barcnt[1]);

    // ---- phase 3: scatter (grid-stride) + flag reset ----
    if (gtid < 256) g_flag[gtid] = 0;   // all lookbacks completed before barrier
    for (int e = gtid; e < N_EDGES; e += BUILD_THREADS) {
        int s = ei[e];
        int d = ei[N_EDGES + e];
        float k0 = Kw[e];
        float k1 = Kw[N_EDGES + e];
        int p = atomicAdd(&g_cursor[d], 1);
        g_src[p] = s;
        g_kw[p] = make_float2(k0, k1);
    }
}

// ---------------- layer 0: conv (d=8, nk=2) ----------------
// warp per node: lanes = 8 features x 4 edge-subsets (MLP=4)
__global__ void k_conv0(const float* __restrict__ x) {
    if (blockIdx.x == 0 && threadIdx.x == 0) {  // reset build barriers for next replay
        g_barcnt[0] = 0;
        g_barcnt[1] = 0;
    }
    int warp = threadIdx.x >> 5, lane = threadIdx.x & 31;
    int node = blockIdx.x * 8 + warp;
    if (node >= N_NODES) return;
    int f = lane & 7, sub = lane >> 3;
    int beg = g_off[node], end = g_off[node + 1];
    float a0 = 0.f, a1 = 0.f;
    for (int k = beg + sub; k < end; k += 4) {
        int s = g_src[k];
        float2 kw = g_kw[k];
        float xv = x[s * 8 + f];
        a0 = fmaf(kw.x, xv, a0);
        a1 = fmaf(kw.y, xv, a1);
    }
    a0 += __shfl_xor_sync(0xffffffffu, a0, 8);
    a0 += __shfl_xor_sync(0xffffffffu, a0, 16);
    a1 += __shfl_xor_sync(0xffffffffu, a1, 8);
    a1 += __shfl_xor_sync(0xffffffffu, a1, 16);
    if (sub == 0) {
        g_h16[node * 16 + f]     = a0;
        g_h16[node * 16 + 8 + f] = a1;
    }
}

// ---------------- layer 0: MLP 16->32 + L2 norm ----------------
__global__ void k_mlp0(const float* __restrict__ W0, const float* __restrict__ b0) {
    __shared__ float W0s[512];
    __shared__ float b0s[32];
    for (int i = threadIdx.x; i < 512; i += blockDim.x) W0s[i] = W0[i];
    if (threadIdx.x < 32) b0s[threadIdx.x] = b0[threadIdx.x];
    __syncthreads();
    int node = blockIdx.x * blockDim.x + threadIdx.x;
    if (node >= N_NODES) return;
    float h[16];
    const float4* hp = (const float4*)&g_h16[node * 16];
#pragma unroll
    for (int j = 0; j < 4; j++) {
        float4 v = hp[j];
        h[4 * j] = v.x; h[4 * j + 1] = v.y; h[4 * j + 2] = v.z; h[4 * j + 3] = v.w;
    }
    float o[32];
    float ss = 0.f;
#pragma unroll
    for (int j = 0; j < 32; j++) {
        float acc = b0s[j];
#pragma unroll
        for (int i = 0; i < 16; i++) acc = fmaf(h[i], W0s[i * 32 + j], acc);
        o[j] = acc;
        ss += acc * acc;
    }
    float inv = 1.f / fmaxf(sqrtf(ss), 1e-12f);
    float4* op = (float4*)&g_h32[node * 32];
#pragma unroll
    for (int j = 0; j < 8; j++)
        op[j] = make_float4(o[4 * j] * inv, o[4 * j + 1] * inv, o[4 * j + 2] * inv, o[4 * j + 3] * inv);
}

// ---------------- layer 1: conv (d=32, nk=2) ----------------
// warp per node; 128B coalesced gathers; 4-edge batches
__global__ void k_conv1() {
    int warp = threadIdx.x >> 5, lane = threadIdx.x & 31;
    int node = blockIdx.x * 8 + warp;
    if (node >= N_NODES) return;
    int beg = g_off[node], end = g_off[node + 1];
    float a0 = 0.f, a1 = 0.f;
    int k = beg;
    for (; k + 4 <= end; k += 4) {
        int s0 = g_src[k], s1 = g_src[k + 1], s2 = g_src[k + 2], s3 = g_src[k + 3];
        float2 w0 = g_kw[k], w1 = g_kw[k + 1], w2 = g_kw[k + 2], w3 = g_kw[k + 3];
        float v0 = g_h32[s0 * 32 + lane];
        float v1 = g_h32[s1 * 32 + lane];
        float v2 = g_h32[s2 * 32 + lane];
        float v3 = g_h32[s3 * 32 + lane];
        a0 = fmaf(w0.x, v0, a0); a1 = fmaf(w0.y, v0, a1);
        a0 = fmaf(w1.x, v1, a0); a1 = fmaf(w1.y, v1, a1);
        a0 = fmaf(w2.x, v2, a0); a1 = fmaf(w2.y, v2, a1);
        a0 = fmaf(w3.x, v3, a0); a1 = fmaf(w3.y, v3, a1);
    }
    for (; k < end; k++) {
        int s = g_src[k];
        float2 w = g_kw[k];
        float v = g_h32[s * 32 + lane];
        a0 = fmaf(w.x, v, a0);
        a1 = fmaf(w.y, v, a1);
    }
    g_h64[node * 64 + lane]      = a0;
    g_h64[node * 64 + 32 + lane] = a1;
}

// ---------------- layer 1: MLP 64->128 (ReLU) ->64 + L2 norm ----------------
// thread per node; h/out register-resident as f32x2 pairs; weights broadcast from smem
__global__ void __launch_bounds__(128) k_mlp1(
    const float* __restrict__ W1, const float* __restrict__ b1,
    const float* __restrict__ W2, const float* __restrict__ b2,
    float* __restrict__ out)
{
    extern __shared__ float smem[];
    float* W1t = smem;          // [128][64] : W1t[o*64+i] = W1[i*128+o]
    float* W2s = smem + 8192;   // [128][64] : as-is
    float* b1s = smem + 16384;  // [128]
    float* b2s = smem + 16512;  // [64]

    for (int idx = threadIdx.x; idx < 8192; idx += blockDim.x) {
        int i = idx >> 7, o = idx & 127;
        W1t[o * 64 + i] = W1[idx];
    }
    for (int idx = threadIdx.x; idx < 8192; idx += blockDim.x) W2s[idx] = W2[idx];
    for (int idx = threadIdx.x; idx < 128; idx += blockDim.x) b1s[idx] = b1[idx];
    for (int idx = threadIdx.x; idx < 64; idx += blockDim.x) b2s[idx] = b2[idx];
    __syncthreads();

    int node = blockIdx.x * blockDim.x + threadIdx.x;
    if (node >= N_NODES) return;

    ull h2[32];
    const ulonglong2* hp = (const ulonglong2*)&g_h64[node * 64];
#pragma unroll
    for (int j = 0; j < 16; j++) {
        ulonglong2 v = hp[j];
        h2[2 * j] = v.x;
        h2[2 * j + 1] = v.y;
    }
    ull out2[32];
#pragma unroll
    for (int m = 0; m < 32; m++) out2[m] = pack2(b2s[2 * m], b2s[2 * m + 1]);

    for (int o = 0; o < 128; o++) {
        const ulonglong2* w1 = (const ulonglong2*)&W1t[o * 64];
        ull a0 = pack2(b1s[o], 0.f);
        ull a1 = pack2(0.f, 0.f);
        ull a2 = pack2(0.f, 0.f);
        ull a3 = pack2(0.f, 0.f);
#pragma unroll
        for (int j = 0; j < 8; j++) {
            ulonglong2 w = w1[j];
            a0 = fma2(h2[2 * j], w.x, a0);
            a1 = fma2(h2[2 * j + 1], w.y, a1);
        }
#pragma unroll
        for (int j = 8; j < 16; j++) {
            ulonglong2 w = w1[j];
            a2 = fma2(h2[2 * j], w.x, a2);
            a3 = fma2(h2[2 * j + 1], w.y, a3);
        }
        float2 pa = unpack2(a0), pb = unpack2(a1), pc = unpack2(a2), pd = unpack2(a3);
        float hid = ((pa.x + pa.y) + (pb.x + pb.y)) + ((pc.x + pc.y) + (pd.x + pd.y));
        hid = fmaxf(hid, 0.f);
        ull hh = pack2(hid, hid);
        const ulonglong2* w2 = (const ulonglong2*)&W2s[o * 64];
#pragma unroll
        for (int j = 0; j < 16; j++) {
            ulonglong2 w = w2[j];
            out2[2 * j]     = fma2(hh, w.x, out2[2 * j]);
            out2[2 * j + 1] = fma2(hh, w.y, out2[2 * j + 1]);
        }
    }

    float ss = 0.f;
    float2 vals[32];
#pragma unroll
    for (int m = 0; m < 32; m++) {
        float2 v = unpack2(out2[m]);
        vals[m] = v;
        ss += v.x * v.x + v.y * v.y;
    }
    float inv = 1.f / fmaxf(sqrtf(ss), 1e-12f);
    float2* op = (float2*)&out[node * 64];
#pragma unroll
    for (int m = 0; m < 32; m++)
        op[m] = make_float2(vals[m].x * inv, vals[m].y * inv);
}

// ---------------- launch ----------------
extern "C" void kernel_launch(void* const* d_in, const int* in_sizes, int n_in,
                              void* d_out, int out_size) {
    const float* x  = (const float*)d_in[0];
    const int*   ei = (const int*)d_in[1];
    const float* Kw = (const float*)d_in[2];
    const float* W0 = (const float*)d_in[3];
    const float* b0 = (const float*)d_in[4];
    const float* W1 = (const float*)d_in[5];
    const float* b1 = (const float*)d_in[6];
    const float* W2 = (const float*)d_in[7];
    const float* b2 = (const float*)d_in[8];
    float* out = (float*)d_out;

    const int mlp1_smem = (8192 + 8192 + 128 + 64) * 4;  // 66304 B
    cudaFuncSetAttribute(k_mlp1, cudaFuncAttributeMaxDynamicSharedMemorySize, mlp1_smem);

    k_build<<<SCAN_BLOCKS, 256>>>(ei, Kw);   // 1  (hist + scan + scatter)
    k_conv0<<<25000, 256>>>(x);              // 2
    k_mlp0<<<782, 256>>>(W0, b0);            // 3
    k_conv1<<<25000, 256>>>();               // 4  <- ncu capture slot
    k_mlp1<<<1563, 128, mlp1_smem>>>(W1, b1, W2, b2, out);  // 5
}

// round 7
// speedup vs baseline: 1.1862x; 1.1862x over previous
#include <cuda_runtime.h>

#define N_NODES 200000
#define N_EDGES 3200000
#define SCAN_BLOCKS 196   // ceil(200000 / 1024)

// ---------------- scratch (device globals; zero-initialized at module load) ----------------
__device__ __align__(16) int    g_deg[N_NODES];      // invariant: zero at kernel_launch entry
__device__ __align__(16) int    g_off[N_NODES + 1];
__device__ __align__(16) int    g_cursor[N_NODES];
__device__ __align__(16) int    g_flag[256];         // invariant: zero at kernel_launch entry
__device__ __align__(16) int    g_src[N_EDGES];
__device__ __align__(16) float2 g_kw[N_EDGES];
__device__ __align__(16) float  g_h16[N_NODES * 16];
__device__ __align__(16) float  g_h32[N_NODES * 32];
__device__ __align__(16) float  g_h64[N_NODES * 64];
__device__ __align__(16) float2 g_hid[64 * N_NODES];  // hidden, transposed: [pair][node]

typedef unsigned long long ull;

__device__ __forceinline__ ull fma2(ull a, ull b, ull c) {
    ull d;
    asm("fma.rn.f32x2 %0, %1, %2, %3;" : "=l"(d) : "l"(a), "l"(b), "l"(c));
    return d;
}
__device__ __forceinline__ ull pack2(float x, float y) {
    ull r;
    asm("mov.b64 %0, {%1, %2};" : "=l"(r) : "f"(x), "f"(y));
    return r;
}
__device__ __forceinline__ float2 unpack2(ull v) {
    float2 r;
    asm("mov.b64 {%0, %1}, %2;" : "=f"(r.x), "=f"(r.y) : "l"(v));
    return r;
}

// ---------------- CSR build ----------------
__global__ void k_hist(const int* __restrict__ ei) {
    int e = blockIdx.x * blockDim.x + threadIdx.x;
    if (e < N_EDGES) atomicAdd(&g_deg[ei[N_EDGES + e]], 1);
}

// single-pass scan: block-local scan + spin-flag lookback over earlier blocks.
__global__ void k_scan() {
    __shared__ int sh[256];
    __shared__ int red[8];
    int t = threadIdx.x;
    int b = blockIdx.x;
    int base = b * 1024 + t * 4;
    int v0 = 0, v1 = 0, v2 = 0, v3 = 0;
    if (base + 0 < N_NODES) v0 = g_deg[base + 0];
    if (base + 1 < N_NODES) v1 = g_deg[base + 1];
    if (base + 2 < N_NODES) v2 = g_deg[base + 2];
    if (base + 3 < N_NODES) v3 = g_deg[base + 3];
    int tot = v0 + v1 + v2 + v3;
    sh[t] = tot;
    __syncthreads();
    for (int d = 1; d < 256; d <<= 1) {
        int xv = (t >= d) ? sh[t - d] : 0;
        __syncthreads();
        sh[t] += xv;
        __syncthreads();
    }
    if (t == 255) ((volatile int*)g_flag)[b] = sh[255] + 1;  // publish block total

    int v = 0;
    if (t < b) {
        volatile int* f = (volatile int*)g_flag;
        int fv;
        while ((fv = f[t]) == 0) {}
        v = fv - 1;
    }
#pragma unroll
    for (int d = 16; d > 0; d >>= 1) v += __shfl_down_sync(0xffffffffu, v, d);
    if ((t & 31) == 0) red[t >> 5] = v;
    __syncthreads();
    int prefix = red[0] + red[1] + red[2] + red[3] + red[4] + red[5] + red[6] + red[7];

    int excl = sh[t] - tot + prefix;
    int e0 = excl, e1 = excl + v0, e2 = excl + v0 + v1, e3 = excl + v0 + v1 + v2;
    if (base + 0 < N_NODES) { g_off[base + 0] = e0; g_cursor[base + 0] = e0; g_deg[base + 0] = 0; }
    if (base + 1 < N_NODES) { g_off[base + 1] = e1; g_cursor[base + 1] = e1; g_deg[base + 1] = 0; }
    if (base + 2 < N_NODES) { g_off[base + 2] = e2; g_cursor[base + 2] = e2; g_deg[base + 2] = 0; }
    if (base + 3 < N_NODES) { g_off[base + 3] = e3; g_cursor[base + 3] = e3; g_deg[base + 3] = 0; }
    if (b == 0 && t == 0) g_off[N_NODES] = N_EDGES;
}

__global__ void k_scatter(const int* __restrict__ ei, const float* __restrict__ Kw) {
    int e = blockIdx.x * blockDim.x + threadIdx.x;
    if (e < 256) g_flag[e] = 0;   // restore scan-flag invariant for next replay
    if (e >= N_EDGES) return;
    int s = ei[e];
    int d = ei[N_EDGES + e];
    float k0 = Kw[e];
    float k1 = Kw[N_EDGES + e];
    int p = atomicAdd(&g_cursor[d], 1);
    g_src[p] = s;
    g_kw[p] = make_float2(k0, k1);
}

// ---------------- layer 0: conv (d=8, nk=2) ----------------
__global__ void k_conv0(const float* __restrict__ x) {
    int warp = threadIdx.x >> 5, lane = threadIdx.x & 31;
    int node = blockIdx.x * 8 + warp;
    if (node >= N_NODES) return;
    int f = lane & 7, sub = lane >> 3;
    int beg = g_off[node], end = g_off[node + 1];
    float a0 = 0.f, a1 = 0.f;
    for (int k = beg + sub; k < end; k += 4) {
        int s = g_src[k];
        float2 kw = g_kw[k];
        float xv = x[s * 8 + f];
        a0 = fmaf(kw.x, xv, a0);
        a1 = fmaf(kw.y, xv, a1);
    }
    a0 += __shfl_xor_sync(0xffffffffu, a0, 8);
    a0 += __shfl_xor_sync(0xffffffffu, a0, 16);
    a1 += __shfl_xor_sync(0xffffffffu, a1, 8);
    a1 += __shfl_xor_sync(0xffffffffu, a1, 16);
    if (sub == 0) {
        g_h16[node * 16 + f]     = a0;
        g_h16[node * 16 + 8 + f] = a1;
    }
}

// ---------------- layer 0: MLP 16->32 + L2 norm ----------------
__global__ void k_mlp0(const float* __restrict__ W0, const float* __restrict__ b0) {
    __shared__ float W0s[512];
    __shared__ float b0s[32];
    for (int i = threadIdx.x; i < 512; i += blockDim.x) W0s[i] = W0[i];
    if (threadIdx.x < 32) b0s[threadIdx.x] = b0[threadIdx.x];
    __syncthreads();
    int node = blockIdx.x * blockDim.x + threadIdx.x;
    if (node >= N_NODES) return;
    float h[16];
    const float4* hp = (const float4*)&g_h16[node * 16];
#pragma unroll
    for (int j = 0; j < 4; j++) {
        float4 v = hp[j];
        h[4 * j] = v.x; h[4 * j + 1] = v.y; h[4 * j + 2] = v.z; h[4 * j + 3] = v.w;
    }
    float o[32];
    float ss = 0.f;
#pragma unroll
    for (int j = 0; j < 32; j++) {
        float acc = b0s[j];
#pragma unroll
        for (int i = 0; i < 16; i++) acc = fmaf(h[i], W0s[i * 32 + j], acc);
        o[j] = acc;
        ss += acc * acc;
    }
    float inv = 1.f / fmaxf(sqrtf(ss), 1e-12f);
    float4* op = (float4*)&g_h32[node * 32];
#pragma unroll
    for (int j = 0; j < 8; j++)
        op[j] = make_float4(o[4 * j] * inv, o[4 * j + 1] * inv, o[4 * j + 2] * inv, o[4 * j + 3] * inv);
}

// ---------------- layer 1: conv (d=32, nk=2) ----------------
__global__ void k_conv1() {
    int warp = threadIdx.x >> 5, lane = threadIdx.x & 31;
    int node = blockIdx.x * 8 + warp;
    if (node >= N_NODES) return;
    int beg = g_off[node], end = g_off[node + 1];
    float a0 = 0.f, a1 = 0.f;
    int k = beg;
    for (; k + 4 <= end; k += 4) {
        int s0 = g_src[k], s1 = g_src[k + 1], s2 = g_src[k + 2], s3 = g_src[k + 3];
        float2 w0 = g_kw[k], w1 = g_kw[k + 1], w2 = g_kw[k + 2], w3 = g_kw[k + 3];
        float v0 = g_h32[s0 * 32 + lane];
        float v1 = g_h32[s1 * 32 + lane];
        float v2 = g_h32[s2 * 32 + lane];
        float v3 = g_h32[s3 * 32 + lane];
        a0 = fmaf(w0.x, v0, a0); a1 = fmaf(w0.y, v0, a1);
        a0 = fmaf(w1.x, v1, a0); a1 = fmaf(w1.y, v1, a1);
        a0 = fmaf(w2.x, v2, a0); a1 = fmaf(w2.y, v2, a1);
        a0 = fmaf(w3.x, v3, a0); a1 = fmaf(w3.y, v3, a1);
    }
    for (; k < end; k++) {
        int s = g_src[k];
        float2 w = g_kw[k];
        float v = g_h32[s * 32 + lane];
        a0 = fmaf(w.x, v, a0);
        a1 = fmaf(w.y, v, a1);
    }
    g_h64[node * 64 + lane]      = a0;
    g_h64[node * 64 + 32 + lane] = a1;
}

// ---------------- layer 1 MLP pass A: 64 -> 128, ReLU ----------------
// thread per node; h[64] in regs (~110 regs total, no spill); W1 in smem as-is;
// 16 outputs per group; hidden written TRANSPOSED as float2 pairs for coalescing.
__global__ void __launch_bounds__(256) k_mlp1a(
    const float* __restrict__ W1, const float* __restrict__ b1)
{
    __shared__ float W1s[64 * 128];
    __shared__ float b1s[128];
    for (int idx = threadIdx.x; idx < 8192; idx += 256) W1s[idx] = W1[idx];
    if (threadIdx.x < 128) b1s[threadIdx.x] = b1[threadIdx.x];
    __syncthreads();

    int node = blockIdx.x * 256 + threadIdx.x;
    if (node >= N_NODES) return;

    float h[64];
    const float4* hp = (const float4*)&g_h64[node * 64];
#pragma unroll
    for (int j = 0; j < 16; j++) {
        float4 v = hp[j];
        h[4 * j] = v.x; h[4 * j + 1] = v.y; h[4 * j + 2] = v.z; h[4 * j + 3] = v.w;
    }

#pragma unroll 1
    for (int g = 0; g < 8; g++) {          // 8 groups x 16 outputs
        int ob = g * 16;
        ull acc[8];
#pragma unroll
        for (int j = 0; j < 8; j++) acc[j] = pack2(b1s[ob + 2 * j], b1s[ob + 2 * j + 1]);
#pragma unroll
        for (int i = 0; i < 64; i++) {
            ull hh = pack2(h[i], h[i]);
            const ulonglong2* wr = (const ulonglong2*)&W1s[i * 128 + ob];
            ulonglong2 wa = wr[0], wb = wr[1], wc = wr[2], wd = wr[3];
            acc[0] = fma2(hh, wa.x, acc[0]); acc[1] = fma2(hh, wa.y, acc[1]);
            acc[2] = fma2(hh, wb.x, acc[2]); acc[3] = fma2(hh, wb.y, acc[3]);
            acc[4] = fma2(hh, wc.x, acc[4]); acc[5] = fma2(hh, wc.y, acc[5]);
            acc[6] = fma2(hh, wd.x, acc[6]); acc[7] = fma2(hh, wd.y, acc[7]);
        }
#pragma unroll
        for (int j = 0; j < 8; j++) {
            float2 v = unpack2(acc[j]);
            g_hid[(g * 8 + j) * N_NODES + node] =
                make_float2(fmaxf(v.x, 0.f), fmaxf(v.y, 0.f));
        }
    }
}

// ---------------- layer 1 MLP pass B: 128 -> 64 + L2 norm ----------------
// thread per node; 32 output-pair accumulators (~100 regs, no spill);
// hidden streamed coalesced in chunks of 8 pairs; W2 rows broadcast from smem.
__global__ void __launch_bounds__(256) k_mlp1b(
    const float* __restrict__ W2, const float* __restrict__ b2,
    float* __restrict__ out)
{
    __shared__ float W2s[128 * 64];
    __shared__ float b2s[64];
    for (int idx = threadIdx.x; idx < 8192; idx += 256) W2s[idx] = W2[idx];
    if (threadIdx.x < 64) b2s[threadIdx.x] = b2[threadIdx.x];
    __syncthreads();

    int node = blockIdx.x * 256 + threadIdx.x;
    if (node >= N_NODES) return;

    ull out2[32];
#pragma unroll
    for (int m = 0; m < 32; m++) out2[m] = pack2(b2s[2 * m], b2s[2 * m + 1]);

#pragma unroll 1
    for (int c = 0; c < 8; c++) {          // 8 chunks x 8 hidden-pairs (16 rows)
        float2 hp[8];
#pragma unroll
        for (int q = 0; q < 8; q++) hp[q] = g_hid[(c * 8 + q) * N_NODES + node];
#pragma unroll
        for (int q = 0; q < 8; q++) {
            int r0 = (c * 8 + q) * 2;
            ull hh0 = pack2(hp[q].x, hp[q].x);
            const ulonglong2* w0 = (const ulonglong2*)&W2s[r0 * 64];
#pragma unroll
            for (int j = 0; j < 8; j++) {
                ulonglong2 w = w0[j];
                out2[2 * j]     = fma2(hh0, w.x, out2[2 * j]);
                out2[2 * j + 1] = fma2(hh0, w.y, out2[2 * j + 1]);
            }
#pragma unroll
            for (int j = 8; j < 16; j++) {
                ulonglong2 w = w0[j];
                out2[2 * j]     = fma2(hh0, w.x, out2[2 * j]);
                out2[2 * j + 1] = fma2(hh0, w.y, out2[2 * j + 1]);
            }
            ull hh1 = pack2(hp[q].y, hp[q].y);
            const ulonglong2* w1 = (const ulonglong2*)&W2s[(r0 + 1) * 64];
#pragma unroll
            for (int j = 0; j < 16; j++) {
                ulonglong2 w = w1[j];
                out2[2 * j]     = fma2(hh1, w.x, out2[2 * j]);
                out2[2 * j + 1] = fma2(hh1, w.y, out2[2 * j + 1]);
            }
        }
    }

    float ss = 0.f;
#pragma unroll
    for (int m = 0; m < 32; m++) {
        float2 v = unpack2(out2[m]);
        ss += v.x * v.x + v.y * v.y;
    }
    float inv = 1.f / fmaxf(sqrtf(ss), 1e-12f);
    float2* op = (float2*)&out[node * 64];
#pragma unroll
    for (int m = 0; m < 32; m++) {
        float2 v = unpack2(out2[m]);
        op[m] = make_float2(v.x * inv, v.y * inv);
    }
}

// ---------------- launch ----------------
extern "C" void kernel_launch(void* const* d_in, const int* in_sizes, int n_in,
                              void* d_out, int out_size) {
    const float* x  = (const float*)d_in[0];
    const int*   ei = (const int*)d_in[1];
    const float* Kw = (const float*)d_in[2];
    const float* W0 = (const float*)d_in[3];
    const float* b0 = (const float*)d_in[4];
    const float* W1 = (const float*)d_in[5];
    const float* b1 = (const float*)d_in[6];
    const float* W2 = (const float*)d_in[7];
    const float* b2 = (const float*)d_in[8];
    float* out = (float*)d_out;

    k_hist<<<12500, 256>>>(ei);           // 1
    k_scan<<<SCAN_BLOCKS, 256>>>();       // 2
    k_scatter<<<12500, 256>>>(ei, Kw);    // 3
    k_conv0<<<25000, 256>>>(x);           // 4  <- ncu capture slot
    k_mlp0<<<782, 256>>>(W0, b0);         // 5
    k_conv1<<<25000, 256>>>();            // 6
    k_mlp1a<<<782, 256>>>(W1, b1);        // 7
    k_mlp1b<<<782, 256>>>(W2, b2, out);   // 8
}